// round 15
// baseline (speedup 1.0000x reference)
#include <cuda_runtime.h>
#include <cuda_bf16.h>
#include <math.h>
#include <stdint.h>

#define FEAT      128
#define N_RELS    8
#define MAX_NODES 100000
#define BK        32
#define ASTRIDE   40            // bf16 elems per smem row (32 + 8 pad -> 80B)

// ---------------------------------------------------------------------------
// Scratch (__device__ globals: allocation-free rule)
// ---------------------------------------------------------------------------
__device__ float g_h_all[(size_t)MAX_NODES * N_RELS * FEAT];  // [n][r][f]
__device__ float g_gate [(size_t)MAX_NODES * N_RELS];
__device__ __align__(16) __nv_bfloat16 g_WT_hi[N_RELS * FEAT * FEAT]; // [r][f][d]
__device__ __align__(16) __nv_bfloat16 g_WT_lo[N_RELS * FEAT * FEAT];
__device__ __align__(16) __nv_bfloat16 g_Ahi[(size_t)MAX_NODES * FEAT]; // h hi split
__device__ __align__(16) __nv_bfloat16 g_Alo[(size_t)MAX_NODES * FEAT]; // h lo split

// mma.sync bf16 (family-target safe; no tcgen05 anywhere)
#define MMA_BF16(d, a, b) \
    asm volatile("mma.sync.aligned.m16n8k16.row.col.f32.bf16.bf16.f32 " \
        "{%0,%1,%2,%3}, {%4,%5,%6,%7}, {%8,%9}, {%0,%1,%2,%3};" \
        : "+f"((d)[0]), "+f"((d)[1]), "+f"((d)[2]), "+f"((d)[3]) \
        : "r"((a)[0]), "r"((a)[1]), "r"((a)[2]), "r"((a)[3]), \
          "r"((b)[0]), "r"((b)[1]))

__device__ __forceinline__ void ldsm_x4(uint32_t& r0, uint32_t& r1,
                                        uint32_t& r2, uint32_t& r3, uint32_t addr) {
    asm volatile("ldmatrix.sync.aligned.m8n8.x4.shared.b16 {%0,%1,%2,%3}, [%4];"
                 : "=r"(r0), "=r"(r1), "=r"(r2), "=r"(r3) : "r"(addr));
}

// ---------------------------------------------------------------------------
// W prep: transpose + bf16 hi/lo split.  out[r][f][d] from W[r][d][f]
// ---------------------------------------------------------------------------
__global__ void rgcn_wprep(const float* __restrict__ W) {
    int idx = blockIdx.x * blockDim.x + threadIdx.x;
    if (idx >= N_RELS * FEAT * FEAT) return;
    int d = idx & 127, f = (idx >> 7) & 127, r = idx >> 14;
    float w = W[((size_t)r * FEAT + d) * FEAT + f];
    __nv_bfloat16 hi = __float2bfloat16(w);
    float lo = w - __bfloat162float(hi);
    g_WT_hi[idx] = hi;
    g_WT_lo[idx] = __float2bfloat16(lo);
}

// A prep: bf16 hi/lo split of h (done once, not once per rel)
__global__ void rgcn_aprep(const float* __restrict__ h, int n_elems) {
    int idx = blockIdx.x * blockDim.x + threadIdx.x;
    if (idx >= n_elems) return;
    float x = h[idx];
    __nv_bfloat16 hi = __float2bfloat16(x);
    g_Ahi[idx] = hi;
    g_Alo[idx] = __float2bfloat16(x - __bfloat162float(hi));
}

// ---------------------------------------------------------------------------
// Tensor GEMM (3xBF16, ldmatrix): h_all[m][r][f] = h[m][:] @ W[r][:][f]
// CTA: 128x128 tile for one rel. 8 warps (4m x 2n), warp tile 32x64.
// ---------------------------------------------------------------------------
__global__ __launch_bounds__(256) void rgcn_gemm_mma(const __nv_bfloat16* __restrict__ Ahi,
                                                     const __nv_bfloat16* __restrict__ Alo,
                                                     const __nv_bfloat16* __restrict__ WThi,
                                                     const __nv_bfloat16* __restrict__ WTlo,
                                                     int n_nodes)
{
    __shared__ __align__(16) __nv_bfloat16 sAhi[128 * ASTRIDE];
    __shared__ __align__(16) __nv_bfloat16 sAlo[128 * ASTRIDE];
    __shared__ __align__(16) __nv_bfloat16 sBhi[128 * ASTRIDE];
    __shared__ __align__(16) __nv_bfloat16 sBlo[128 * ASTRIDE];

    const int tid  = threadIdx.x;
    const int lane = tid & 31;
    const int warp = tid >> 5;
    const int wm   = (warp & 3) * 32;   // warp m offset (4 warps along M)
    const int wn   = (warp >> 2) * 64;  // warp n offset (2 warps along N)
    const int g    = lane >> 2;         // 0..7
    const int tg   = lane & 3;          // 0..3

    const int r     = blockIdx.x;       // rel fast -> 8 CTAs share A via L2
    const int mBase = blockIdx.y * 128;

    // loader mapping: thread t -> rows (t>>2, t>>2+64), 16B quarter (t&3)
    const int ldRow = tid >> 2;         // 0..63
    const int ldQ   = (tid & 3) * 8;    // bf16 offset 0,8,16,24

    // ldmatrix per-lane base addresses (ks=0 chunk-local)
    const uint32_t aHiB = (uint32_t)__cvta_generic_to_shared(sAhi);
    const uint32_t aLoB = (uint32_t)__cvta_generic_to_shared(sAlo);
    const uint32_t bHiB = (uint32_t)__cvta_generic_to_shared(sBhi);
    const uint32_t bLoB = (uint32_t)__cvta_generic_to_shared(sBlo);
    const uint32_t aOff = (uint32_t)(((wm + (lane & 15)) * ASTRIDE + (lane >> 4) * 8) * 2);
    const uint32_t bOff = (uint32_t)(((wn + (lane & 7) + ((lane >> 4) & 1) * 8) * ASTRIDE +
                                      ((lane >> 3) & 1) * 8) * 2);

    float acc[2][8][4] = {};

    for (int c = 0; c < 4; c++) {
        // ---- gmem prefetch into regs (overlaps previous chunk's MMAs) ----
        uint4 vah[2], val[2], vbh[2], vbl[2];
#pragma unroll
        for (int hblk = 0; hblk < 2; hblk++) {
            const int row = hblk * 64 + ldRow;
            const int m   = mBase + row;
            vah[hblk] = make_uint4(0, 0, 0, 0);
            val[hblk] = make_uint4(0, 0, 0, 0);
            if (m < n_nodes) {
                const size_t ai = (size_t)m * FEAT + c * BK + ldQ;
                vah[hblk] = *(const uint4*)(Ahi + ai);
                val[hblk] = *(const uint4*)(Alo + ai);
            }
            const size_t bi = ((size_t)(r * 128 + row)) * FEAT + c * BK + ldQ;
            vbh[hblk] = *(const uint4*)(WThi + bi);
            vbl[hblk] = *(const uint4*)(WTlo + bi);
        }

        __syncthreads();   // previous chunk's fragment reads are done
#pragma unroll
        for (int hblk = 0; hblk < 2; hblk++) {
            const int row = hblk * 64 + ldRow;
            *(uint4*)&sAhi[row * ASTRIDE + ldQ] = vah[hblk];
            *(uint4*)&sAlo[row * ASTRIDE + ldQ] = val[hblk];
            *(uint4*)&sBhi[row * ASTRIDE + ldQ] = vbh[hblk];
            *(uint4*)&sBlo[row * ASTRIDE + ldQ] = vbl[hblk];
        }
        __syncthreads();

        // ---- MMA: 2 ksteps x 3 split-terms x (2m x 8n), fragments via ldmatrix ----
#pragma unroll
        for (int ks = 0; ks < 2; ks++) {
            const uint32_t kByte = (uint32_t)(ks * 16 * 2);
            uint32_t ahi[2][4], alo[2][4], bhi[8][2], blo[8][2];
#pragma unroll
            for (int mt = 0; mt < 2; mt++) {
                const uint32_t mo = aOff + (uint32_t)(mt * 16 * ASTRIDE * 2) + kByte;
                ldsm_x4(ahi[mt][0], ahi[mt][1], ahi[mt][2], ahi[mt][3], aHiB + mo);
                ldsm_x4(alo[mt][0], alo[mt][1], alo[mt][2], alo[mt][3], aLoB + mo);
            }
#pragma unroll
            for (int p = 0; p < 4; p++) {     // pair p covers nt = 2p, 2p+1
                const uint32_t no = bOff + (uint32_t)(p * 16 * ASTRIDE * 2) + kByte;
                ldsm_x4(bhi[2*p][0], bhi[2*p][1], bhi[2*p+1][0], bhi[2*p+1][1], bHiB + no);
                ldsm_x4(blo[2*p][0], blo[2*p][1], blo[2*p+1][0], blo[2*p+1][1], bLoB + no);
            }
#pragma unroll
            for (int mt = 0; mt < 2; mt++)
#pragma unroll
                for (int nt = 0; nt < 8; nt++) {
                    MMA_BF16(acc[mt][nt], ahi[mt], bhi[nt]);
                    MMA_BF16(acc[mt][nt], ahi[mt], blo[nt]);
                    MMA_BF16(acc[mt][nt], alo[mt], bhi[nt]);
                }
        }
    }

    // ---- epilogue: c-frag rows (g, g+8), cols tg*2..+1 per n-tile ----
#pragma unroll
    for (int mt = 0; mt < 2; mt++) {
#pragma unroll
        for (int ro = 0; ro < 2; ro++) {
            const int m = mBase + wm + mt * 16 + g + ro * 8;
            if (m < n_nodes) {
                float* dstp = g_h_all + ((size_t)m * N_RELS + r) * FEAT;
#pragma unroll
                for (int nt = 0; nt < 8; nt++) {
                    float2 v;
                    v.x = acc[mt][nt][ro * 2 + 0];
                    v.y = acc[mt][nt][ro * 2 + 1];
                    *(float2*)(dstp + wn + nt * 8 + tg * 2) = v;
                }
            }
        }
    }
}

// ---------------------------------------------------------------------------
// Gate GEMV (warp per node)
// ---------------------------------------------------------------------------
__global__ __launch_bounds__(256) void rgcn_gate(const float* __restrict__ h,
                                                 const float* __restrict__ gw,
                                                 int n_nodes)
{
    __shared__ float sgw[N_RELS][FEAT];
    for (int i = threadIdx.x; i < N_RELS * FEAT; i += blockDim.x)
        sgw[i / FEAT][i % FEAT] = gw[i];
    __syncthreads();

    int warp = (blockIdx.x * blockDim.x + threadIdx.x) >> 5;
    int lane = threadIdx.x & 31;
    if (warp >= n_nodes) return;

    float4 hv = *(const float4*)(h + (size_t)warp * FEAT + lane * 4);
#pragma unroll
    for (int r = 0; r < N_RELS; r++) {
        float4 wv = *(const float4*)&sgw[r][lane * 4];
        float d = hv.x * wv.x + hv.y * wv.y + hv.z * wv.z + hv.w * wv.w;
#pragma unroll
        for (int off = 16; off; off >>= 1)
            d += __shfl_xor_sync(0xffffffffu, d, off);
        if (lane == 0) g_gate[(size_t)warp * N_RELS + r] = d;
    }
}

// ---------------------------------------------------------------------------
// Edge gather/scatter (warp per edge). One red.global.add.v4.f32 per lane.
// ---------------------------------------------------------------------------
__global__ __launch_bounds__(256) void rgcn_edge(const int* __restrict__ src,
                                                 const int* __restrict__ dst,
                                                 const int* __restrict__ rel,
                                                 const float* __restrict__ norm,
                                                 float* __restrict__ out,
                                                 int n_edges)
{
    int warp = (blockIdx.x * blockDim.x + threadIdx.x) >> 5;
    int lane = threadIdx.x & 31;
    if (warp >= n_edges) return;

    int s = src[warp], d = dst[warp], r = rel[warp];
    float gv    = g_gate[(size_t)s * N_RELS + r];
    float scale = norm[warp] / (1.0f + __expf(-gv));

    const float4* hp = (const float4*)(g_h_all + ((size_t)s * N_RELS + r) * FEAT);
    float4 v = hp[lane];

    float* o = out + (size_t)d * FEAT + lane * 4;   // 16B aligned
    asm volatile("red.global.add.v4.f32 [%0], {%1, %2, %3, %4};"
                 :: "l"(o), "f"(v.x * scale), "f"(v.y * scale),
                    "f"(v.z * scale), "f"(v.w * scale)
                 : "memory");
}

__global__ void rgcn_relu(float4* out, int n4)
{
    int i = blockIdx.x * blockDim.x + threadIdx.x;
    if (i < n4) {
        float4 v = out[i];
        v.x = fmaxf(v.x, 0.f); v.y = fmaxf(v.y, 0.f);
        v.z = fmaxf(v.z, 0.f); v.w = fmaxf(v.w, 0.f);
        out[i] = v;
    }
}

extern "C" void kernel_launch(void* const* d_in, const int* in_sizes, int n_in,
                              void* d_out, int out_size)
{
    const float* h    = (const float*)d_in[0];
    const float* W    = (const float*)d_in[1];
    const float* gw   = (const float*)d_in[2];
    const float* norm = (const float*)d_in[3];
    const int*   src  = (const int*)  d_in[4];
    const int*   dst  = (const int*)  d_in[5];
    const int*   rel  = (const int*)  d_in[6];
    float* out = (float*)d_out;

    const int n_nodes = in_sizes[0] / FEAT;
    const int n_edges = in_sizes[4];

    cudaMemsetAsync(out, 0, (size_t)out_size * sizeof(float));

    rgcn_wprep<<<(N_RELS * FEAT * FEAT + 255) / 256, 256>>>(W);
    rgcn_aprep<<<((size_t)n_nodes * FEAT + 255) / 256, 256>>>(h, n_nodes * FEAT);

    __nv_bfloat16 *wthi_p = nullptr, *wtlo_p = nullptr, *ahi_p = nullptr, *alo_p = nullptr;
    cudaGetSymbolAddress((void**)&wthi_p, g_WT_hi);
    cudaGetSymbolAddress((void**)&wtlo_p, g_WT_lo);
    cudaGetSymbolAddress((void**)&ahi_p,  g_Ahi);
    cudaGetSymbolAddress((void**)&alo_p,  g_Alo);

    dim3 ggrid(N_RELS, (n_nodes + 127) / 128);
    rgcn_gemm_mma<<<ggrid, 256>>>(ahi_p, alo_p, wthi_p, wtlo_p, n_nodes);

    rgcn_gate<<<((size_t)n_nodes * 32 + 255) / 256, 256>>>(h, gw, n_nodes);
    rgcn_edge<<<((size_t)n_edges * 32 + 255) / 256, 256>>>(src, dst, rel, norm, out, n_edges);

    int n4 = out_size / 4;
    rgcn_relu<<<(n4 + 255) / 256, 256>>>((float4*)out, n4);
}